// round 1
// baseline (speedup 1.0000x reference)
#include <cuda_runtime.h>
#include <cuda_bf16.h>

// Scratch: __device__ globals (no allocations allowed).
#define MAXN 100352   // >= 100,000 nodes, padded
#define HID  128

__device__ float g_deg[MAXN];   // degree (init 1.0 for self loop)
__device__ float g_dinv[MAXN];  // deg^-1/2
__device__ float g_s[MAXN];     // s[c] = sum_e norm*x[row]  (incl self loop)
__device__ float g_w[MAXN];     // w[i] = sum_e norm          (incl self loop)
__device__ float g_v[HID];      // v[k] = sum_i w[i]*relu(s[i]*W1[k]+b1[k])

// ---------------------------------------------------------------------------
// 1) init: deg = 1 (self loop), v = 0
__global__ void k_init(int n) {
    int i = blockIdx.x * blockDim.x + threadIdx.x;
    if (i < n) g_deg[i] = 1.0f;
    if (i < HID) g_v[i] = 0.0f;
}

// 2) degree scatter over destinations
__global__ void k_deg(const int* __restrict__ col, int E) {
    int t = blockIdx.x * blockDim.x + threadIdx.x;
    int i = t * 4;
    if (i + 3 < E) {
        int4 c = *reinterpret_cast<const int4*>(col + i);
        atomicAdd(&g_deg[c.x], 1.0f);
        atomicAdd(&g_deg[c.y], 1.0f);
        atomicAdd(&g_deg[c.z], 1.0f);
        atomicAdd(&g_deg[c.w], 1.0f);
    } else if (i < E) {
        for (; i < E; ++i) atomicAdd(&g_deg[col[i]], 1.0f);
    }
}

// 3) dinv = rsqrt(deg); seed s,w with the self-loop contribution (norm = dinv^2)
__global__ void k_dinv(const float* __restrict__ x, int n) {
    int i = blockIdx.x * blockDim.x + threadIdx.x;
    if (i >= n) return;
    float di = rsqrtf(g_deg[i]);
    g_dinv[i] = di;
    float d2 = di * di;
    g_s[i] = d2 * x[i];
    g_w[i] = d2;
}

// 4) edge pass: nr = dinv[r]*dinv[c];  s[c] += nr*x[r];  w[r] += nr
__global__ void k_edge(const int* __restrict__ row, const int* __restrict__ col,
                       const float* __restrict__ x, int E) {
    int t = blockIdx.x * blockDim.x + threadIdx.x;
    int i = t * 4;
    if (i + 3 < E) {
        int4 r4 = *reinterpret_cast<const int4*>(row + i);
        int4 c4 = *reinterpret_cast<const int4*>(col + i);
        {
            float nr = g_dinv[r4.x] * g_dinv[c4.x];
            atomicAdd(&g_s[c4.x], nr * x[r4.x]);
            atomicAdd(&g_w[r4.x], nr);
        }
        {
            float nr = g_dinv[r4.y] * g_dinv[c4.y];
            atomicAdd(&g_s[c4.y], nr * x[r4.y]);
            atomicAdd(&g_w[r4.y], nr);
        }
        {
            float nr = g_dinv[r4.z] * g_dinv[c4.z];
            atomicAdd(&g_s[c4.z], nr * x[r4.z]);
            atomicAdd(&g_w[r4.z], nr);
        }
        {
            float nr = g_dinv[r4.w] * g_dinv[c4.w];
            atomicAdd(&g_s[c4.w], nr * x[r4.w]);
            atomicAdd(&g_w[r4.w], nr);
        }
    } else if (i < E) {
        for (; i < E; ++i) {
            int r = row[i], c = col[i];
            float nr = g_dinv[r] * g_dinv[c];
            atomicAdd(&g_s[c], nr * x[r]);
            atomicAdd(&g_w[r], nr);
        }
    }
}

// 5) v[k] = sum_i w[i] * relu(s[i]*W1[k] + b1[k])
//    128 threads per block (thread = feature k), nodes tiled through smem.
#define VTILE 512
__global__ void k_vred(const float* __restrict__ W1, const float* __restrict__ b1,
                       int n) {
    __shared__ float ss[VTILE];
    __shared__ float sw[VTILE];
    int k = threadIdx.x;          // 0..127
    float w1k = W1[k];
    float b1k = b1[k];
    float acc = 0.0f;
    for (int base = blockIdx.x * VTILE; base < n; base += gridDim.x * VTILE) {
        int cnt = min(VTILE, n - base);
        for (int j = k; j < cnt; j += HID) {
            ss[j] = g_s[base + j];
            sw[j] = g_w[base + j];
        }
        __syncthreads();
        #pragma unroll 4
        for (int j = 0; j < cnt; ++j) {
            acc += sw[j] * fmaxf(ss[j] * w1k + b1k, 0.0f);
        }
        __syncthreads();
    }
    atomicAdd(&g_v[k], acc);
}

// 6) out[o] = (1/n) * sum_k v[k]*W2[k,o] + b2[o]
__global__ void k_out(const float* __restrict__ W2, const float* __restrict__ b2,
                      float* __restrict__ out, int n, int od) {
    __shared__ float vs[HID];
    if (threadIdx.x < HID) vs[threadIdx.x] = g_v[threadIdx.x];
    __syncthreads();
    int o = blockIdx.x * blockDim.x + threadIdx.x;
    if (o >= od) return;
    float acc = 0.0f;
    #pragma unroll 8
    for (int kk = 0; kk < HID; ++kk) {
        acc += vs[kk] * W2[kk * od + o];
    }
    out[o] = acc * (1.0f / (float)n) + b2[o];
}

// ---------------------------------------------------------------------------
extern "C" void kernel_launch(void* const* d_in, const int* in_sizes, int n_in,
                              void* d_out, int out_size) {
    const float* x   = (const float*)d_in[0];   // [N]
    const int*   ei  = (const int*)d_in[1];     // [2, E] row-major
    const float* W1  = (const float*)d_in[2];   // [128]
    const float* b1  = (const float*)d_in[3];   // [128]
    const float* W2  = (const float*)d_in[4];   // [128, OUT]
    const float* b2  = (const float*)d_in[5];   // [OUT]
    float* out = (float*)d_out;

    int N = in_sizes[0];
    int E = in_sizes[1] / 2;
    int OD = in_sizes[5];
    const int* row = ei;
    const int* col = ei + E;

    int tb = 256;
    k_init<<<(N + tb - 1) / tb, tb>>>(N);

    int nt4 = (E + 3) / 4;
    k_deg<<<(nt4 + tb - 1) / tb, tb>>>(col, E);

    k_dinv<<<(N + tb - 1) / tb, tb>>>(x, N);

    k_edge<<<(nt4 + tb - 1) / tb, tb>>>(row, col, x, E);

    k_vred<<<148, HID>>>(W1, b1, N);

    k_out<<<(OD + 511) / 512, 512>>>(W2, b2, out, N, OD);
}

// round 2
// speedup vs baseline: 1.3977x; 1.3977x over previous
#include <cuda_runtime.h>
#include <cuda_bf16.h>

// Scratch: __device__ globals (no allocations allowed).
#define MAXN 100352   // >= 100,000 nodes, padded to /4
#define HID  128

__device__ float g_deg[MAXN];   // degree (init 1.0 for self loop)
__device__ float g_dinv[MAXN];  // deg^-1/2
__device__ float g_dxv[MAXN];   // dinv * x
__device__ float g_u[MAXN];     // u[c] = sum_{e:col=c} dinv[r]*x[r]   (seeded w/ self loop)
__device__ float g_t[MAXN];     // t[r] = sum_{e:row=r} dinv[c]        (seeded w/ self loop)
__device__ float g_v[HID];      // v[k] = sum_i w[i]*relu(s[i]*W1[k]+b1[k])

// ---------------------------------------------------------------------------
// 1) init: deg = 1 (self loop), v = 0  (vectorized; MAXN % 4 == 0, padding harmless)
__global__ void k_init(int n4) {
    int i = blockIdx.x * blockDim.x + threadIdx.x;
    if (i < n4) reinterpret_cast<float4*>(g_deg)[i] = make_float4(1.f, 1.f, 1.f, 1.f);
    if (i < HID) g_v[i] = 0.0f;
}

// 2) degree scatter over destinations (8 edges/thread for MLP)
__global__ void __launch_bounds__(256) k_deg(const int* __restrict__ col, int E) {
    int t = blockIdx.x * blockDim.x + threadIdx.x;
    int i = t * 8;
    if (i + 7 < E) {
        int c[8];
        *reinterpret_cast<int4*>(c)     = *reinterpret_cast<const int4*>(col + i);
        *reinterpret_cast<int4*>(c + 4) = *reinterpret_cast<const int4*>(col + i + 4);
        #pragma unroll
        for (int j = 0; j < 8; ++j) atomicAdd(&g_deg[c[j]], 1.0f);
    } else if (i < E) {
        for (; i < E; ++i) atomicAdd(&g_deg[col[i]], 1.0f);
    }
}

// 3) dinv = rsqrt(deg); precompute dxv = dinv*x; seed u,t with self-loop terms
__global__ void k_dinv(const float* __restrict__ x, int n) {
    int i = blockIdx.x * blockDim.x + threadIdx.x;
    if (i >= n) return;
    float di = rsqrtf(g_deg[i]);
    float dxv = di * x[i];
    g_dinv[i] = di;
    g_dxv[i]  = dxv;
    g_u[i]    = dxv;   // self loop: u[i] += dinv[i]*x[i]
    g_t[i]    = di;    // self loop: t[i] += dinv[i]
}

// 4) edge pass: u[c] += dxv[r];  t[r] += dinv[c]   (2 gathers + 2 reds per edge)
__global__ void __launch_bounds__(256) k_edge(const int* __restrict__ row,
                                              const int* __restrict__ col, int E) {
    int t = blockIdx.x * blockDim.x + threadIdx.x;
    int i = t * 8;
    if (i + 7 < E) {
        int r[8], c[8];
        *reinterpret_cast<int4*>(r)     = *reinterpret_cast<const int4*>(row + i);
        *reinterpret_cast<int4*>(r + 4) = *reinterpret_cast<const int4*>(row + i + 4);
        *reinterpret_cast<int4*>(c)     = *reinterpret_cast<const int4*>(col + i);
        *reinterpret_cast<int4*>(c + 4) = *reinterpret_cast<const int4*>(col + i + 4);
        float dx[8], dc[8];
        #pragma unroll
        for (int j = 0; j < 8; ++j) {   // 16 independent gathers in flight
            dx[j] = __ldg(&g_dxv[r[j]]);
            dc[j] = __ldg(&g_dinv[c[j]]);
        }
        #pragma unroll
        for (int j = 0; j < 8; ++j) {
            atomicAdd(&g_u[c[j]], dx[j]);
            atomicAdd(&g_t[r[j]], dc[j]);
        }
    } else if (i < E) {
        for (; i < E; ++i) {
            int r = row[i], c = col[i];
            atomicAdd(&g_u[c], g_dxv[r]);
            atomicAdd(&g_t[r], g_dinv[c]);
        }
    }
}

// 5) v[k] = sum_i w[i]*relu(s[i]*W1[k]+b1[k]),  s=dinv*u, w=dinv*t (folded here)
#define VTILE 512
__global__ void k_vred(const float* __restrict__ W1, const float* __restrict__ b1,
                       int n) {
    __shared__ float ss[VTILE];
    __shared__ float sw[VTILE];
    int k = threadIdx.x;          // 0..127
    float w1k = W1[k];
    float b1k = b1[k];
    float acc = 0.0f;
    for (int base = blockIdx.x * VTILE; base < n; base += gridDim.x * VTILE) {
        int cnt = min(VTILE, n - base);
        for (int j = k; j < cnt; j += HID) {
            float di = g_dinv[base + j];
            ss[j] = di * g_u[base + j];
            sw[j] = di * g_t[base + j];
        }
        __syncthreads();
        #pragma unroll 4
        for (int j = 0; j < cnt; ++j) {
            acc += sw[j] * fmaxf(ss[j] * w1k + b1k, 0.0f);
        }
        __syncthreads();
    }
    atomicAdd(&g_v[k], acc);
}

// 6) out[o] = (1/n) * sum_k v[k]*W2[k,o] + b2[o]
__global__ void k_out(const float* __restrict__ W2, const float* __restrict__ b2,
                      float* __restrict__ out, int n, int od) {
    __shared__ float vs[HID];
    if (threadIdx.x < HID) vs[threadIdx.x] = g_v[threadIdx.x];
    __syncthreads();
    int o = blockIdx.x * blockDim.x + threadIdx.x;
    if (o >= od) return;
    float acc = 0.0f;
    #pragma unroll 8
    for (int kk = 0; kk < HID; ++kk) {
        acc += vs[kk] * W2[kk * od + o];
    }
    out[o] = acc * (1.0f / (float)n) + b2[o];
}

// ---------------------------------------------------------------------------
extern "C" void kernel_launch(void* const* d_in, const int* in_sizes, int n_in,
                              void* d_out, int out_size) {
    const float* x   = (const float*)d_in[0];   // [N]
    const int*   ei  = (const int*)d_in[1];     // [2, E] row-major
    const float* W1  = (const float*)d_in[2];   // [128]
    const float* b1  = (const float*)d_in[3];   // [128]
    const float* W2  = (const float*)d_in[4];   // [128, OUT]
    const float* b2  = (const float*)d_in[5];   // [OUT]
    float* out = (float*)d_out;

    int N = in_sizes[0];
    int E = in_sizes[1] / 2;
    int OD = in_sizes[5];
    const int* row = ei;
    const int* col = ei + E;

    int tb = 256;
    int n4 = MAXN / 4;
    k_init<<<(n4 + tb - 1) / tb, tb>>>(n4);

    int nt8 = (E + 7) / 8;
    k_deg<<<(nt8 + tb - 1) / tb, tb>>>(col, E);

    k_dinv<<<(N + tb - 1) / tb, tb>>>(x, N);

    k_edge<<<(nt8 + tb - 1) / tb, tb>>>(row, col, E);

    k_vred<<<148, HID>>>(W1, b1, N);

    k_out<<<(OD + 511) / 512, 512>>>(W2, b2, out, N, OD);
}

// round 4
// speedup vs baseline: 1.4480x; 1.0360x over previous
#include <cuda_runtime.h>
#include <cuda_bf16.h>

// Scratch: __device__ globals (no allocations allowed).
#define MAXN 100352   // >= 100,000 nodes, padded to /4
#define HID  128

__device__ float g_deg[MAXN];   // edge-degree (memset 0; +1 self loop applied in rsqrt)
__device__ float g_dinv[MAXN];  // (deg+1)^-1/2
__device__ float g_dxv[MAXN];   // dinv * x
__device__ float g_u[MAXN];     // u[c] = sum dinv[r]*x[r]   (seeded w/ self loop)
__device__ float g_t[MAXN];     // t[r] = sum dinv[c]        (seeded w/ self loop)
__device__ float g_v[HID];      // v[k]
__device__ int   g_ctr;         // last-block counter

// ---------------------------------------------------------------------------
// 1) degree scatter over destinations (8 edges/thread)
__global__ void __launch_bounds__(256) k_deg(const int* __restrict__ col, int E) {
    int t = blockIdx.x * blockDim.x + threadIdx.x;
    int i = t * 8;
    if (i + 7 < E) {
        int c[8];
        *reinterpret_cast<int4*>(c)     = *reinterpret_cast<const int4*>(col + i);
        *reinterpret_cast<int4*>(c + 4) = *reinterpret_cast<const int4*>(col + i + 4);
        #pragma unroll
        for (int j = 0; j < 8; ++j) atomicAdd(&g_deg[c[j]], 1.0f);
    } else if (i < E) {
        for (; i < E; ++i) atomicAdd(&g_deg[col[i]], 1.0f);
    }
}

// 2) dinv = rsqrt(deg+1); dxv = dinv*x; seed u,t with self-loop; zero v & ctr
__global__ void k_dinv(const float* __restrict__ x, int n) {
    int i4 = blockIdx.x * blockDim.x + threadIdx.x;
    int i = i4 * 4;
    if (i + 3 < n) {
        float4 d = *reinterpret_cast<const float4*>(g_deg + i);
        float4 xv = *reinterpret_cast<const float4*>(x + i);
        float4 di, dx;
        di.x = rsqrtf(d.x + 1.0f); di.y = rsqrtf(d.y + 1.0f);
        di.z = rsqrtf(d.z + 1.0f); di.w = rsqrtf(d.w + 1.0f);
        dx.x = di.x * xv.x; dx.y = di.y * xv.y;
        dx.z = di.z * xv.z; dx.w = di.w * xv.w;
        *reinterpret_cast<float4*>(g_dinv + i) = di;
        *reinterpret_cast<float4*>(g_dxv + i)  = dx;
        *reinterpret_cast<float4*>(g_u + i)    = dx;  // self loop: dinv*x
        *reinterpret_cast<float4*>(g_t + i)    = di;  // self loop: dinv
    } else {
        for (; i < n; ++i) {
            float di = rsqrtf(g_deg[i] + 1.0f);
            float dx = di * x[i];
            g_dinv[i] = di; g_dxv[i] = dx; g_u[i] = dx; g_t[i] = di;
        }
    }
    if (i4 < HID / 4) reinterpret_cast<float4*>(g_v)[i4] = make_float4(0.f, 0.f, 0.f, 0.f);
    if (i4 == 0) g_ctr = 0;
}

// 3) edge pass: u[c] += dxv[r]; t[r] += dinv[c]   (12 edges/thread, 24 gathers in flight)
#define EPT 12
__global__ void __launch_bounds__(256) k_edge(const int* __restrict__ row,
                                              const int* __restrict__ col, int E) {
    int t = blockIdx.x * blockDim.x + threadIdx.x;
    int i = t * EPT;
    if (i + EPT - 1 < E) {
        int r[EPT], c[EPT];
        #pragma unroll
        for (int q = 0; q < EPT / 4; ++q) {
            *reinterpret_cast<int4*>(r + q * 4) = *reinterpret_cast<const int4*>(row + i + q * 4);
            *reinterpret_cast<int4*>(c + q * 4) = *reinterpret_cast<const int4*>(col + i + q * 4);
        }
        float dx[EPT], dc[EPT];
        #pragma unroll
        for (int j = 0; j < EPT; ++j) {
            dx[j] = __ldg(&g_dxv[r[j]]);
            dc[j] = __ldg(&g_dinv[c[j]]);
        }
        #pragma unroll
        for (int j = 0; j < EPT; ++j) {
            atomicAdd(&g_u[c[j]], dx[j]);
            atomicAdd(&g_t[r[j]], dc[j]);
        }
    } else if (i < E) {
        int iend = min(i + EPT, E);
        for (; i < iend; ++i) {
            int r = row[i], c = col[i];
            atomicAdd(&g_u[c], g_dxv[r]);
            atomicAdd(&g_t[r], g_dinv[c]);
        }
    }
}

// 4) fused: v[k] = sum_i (dinv*t)[i]*relu((dinv*u)[i]*W1[k]+b1[k]); last block does GEMV out
#define VTILE 256
__global__ void __launch_bounds__(256) k_vred(const float* __restrict__ W1,
                                              const float* __restrict__ b1,
                                              const float* __restrict__ W2,
                                              const float* __restrict__ b2,
                                              float* __restrict__ out,
                                              int n, int od) {
    __shared__ float ss[VTILE];
    __shared__ float sw[VTILE];
    __shared__ int   sLast;
    int tid = threadIdx.x;
    int k = tid & (HID - 1);       // 0..127
    int half = tid >> 7;           // 0 or 1
    float w1k = W1[k];
    float b1k = b1[k];
    float acc = 0.0f;
    for (int base = blockIdx.x * VTILE; base < n; base += gridDim.x * VTILE) {
        int cnt = min(VTILE, n - base);
        for (int j = tid; j < cnt; j += 256) {
            float di = g_dinv[base + j];
            ss[j] = di * g_u[base + j];
            sw[j] = di * g_t[base + j];
        }
        __syncthreads();
        int j0 = half * (VTILE / 2);
        int j1 = min(cnt, j0 + VTILE / 2);
        #pragma unroll 4
        for (int j = j0; j < j1; ++j) {
            acc += sw[j] * fmaxf(ss[j] * w1k + b1k, 0.0f);
        }
        __syncthreads();
    }
    atomicAdd(&g_v[k], acc);
    __threadfence();
    __syncthreads();
    if (tid == 0) sLast = (atomicAdd(&g_ctr, 1) == gridDim.x - 1);
    __syncthreads();
    if (sLast) {
        __shared__ float vs[HID];
        if (tid < HID) vs[tid] = *((volatile float*)&g_v[tid]);
        __syncthreads();
        float inv_n = 1.0f / (float)n;
        for (int o = tid; o < od; o += 256) {
            float a = 0.0f;
            #pragma unroll 8
            for (int kk = 0; kk < HID; ++kk) {
                a += vs[kk] * W2[kk * od + o];
            }
            out[o] = a * inv_n + b2[o];
        }
    }
}

// ---------------------------------------------------------------------------
extern "C" void kernel_launch(void* const* d_in, const int* in_sizes, int n_in,
                              void* d_out, int out_size) {
    const float* x   = (const float*)d_in[0];   // [N]
    const int*   ei  = (const int*)d_in[1];     // [2, E] row-major
    const float* W1  = (const float*)d_in[2];   // [128]
    const float* b1  = (const float*)d_in[3];   // [128]
    const float* W2  = (const float*)d_in[4];   // [128, OUT]
    const float* b2  = (const float*)d_in[5];   // [OUT]
    float* out = (float*)d_out;

    int N = in_sizes[0];
    int E = in_sizes[1] / 2;
    int OD = in_sizes[5];
    const int* row = ei;
    const int* col = ei + E;

    void* degp = nullptr;
    cudaGetSymbolAddress(&degp, g_deg);
    cudaMemsetAsync(degp, 0, (size_t)N * sizeof(float));

    int tb = 256;
    int nt8 = (E + 7) / 8;
    k_deg<<<(nt8 + tb - 1) / tb, tb>>>(col, E);

    int n4 = (N + 3) / 4;
    k_dinv<<<(n4 + tb - 1) / tb, tb>>>(x, N);

    int ntE = (E + EPT - 1) / EPT;
    k_edge<<<(ntE + tb - 1) / tb, tb>>>(row, col, E);

    k_vred<<<592, 256>>>(W1, b1, W2, b2, out, N, OD);
}